// round 8
// baseline (speedup 1.0000x reference)
#include <cuda_runtime.h>
#include <cstdint>

#define NA 256
#define NB 256
#define NV 12
#define ND 512
#define NC 8
#define NW 64
#define NH 256
#define TEMP_INV 0.2f

// ---- scratch (device globals; no allocation allowed) ----
__device__ __align__(16) float g_P[NB * NV * NC * NH];   // 25 MB [b][v][c][h]
__device__ __align__(16) float g_T[NA * NC * NH];        // 2 MB  [a][c][lane*8+k] packed
__device__ float g_invn[NA * NC];                        // 1/||t_chunk||
__device__ float g_G[NB * NC * NV * NV];                 // 1.2 MB chunk Gram
__device__ __align__(16) float g_w[NB * NA * NV];        // 3 MB softmax weights
__device__ __align__(16) float g_cos[NB * NA * NC];      // 2 MB cosine logits

// ---- packed f32x2 helpers ----
__device__ __forceinline__ unsigned long long pk2(float lo, float hi) {
    unsigned long long r;
    asm("mov.b64 %0, {%1, %2};" : "=l"(r) : "f"(lo), "f"(hi));
    return r;
}
__device__ __forceinline__ void upk2(unsigned long long p, float& lo, float& hi) {
    asm("mov.b64 {%0, %1}, %2;" : "=f"(lo), "=f"(hi) : "l"(p));
}
__device__ __forceinline__ unsigned long long ffma2(unsigned long long a, unsigned long long b,
                                                    unsigned long long c) {
    unsigned long long d;
    asm("fma.rn.f32x2 %0, %1, %2, %3;" : "=l"(d) : "l"(a), "l"(b), "l"(c));
    return d;
}
// warp-wide fp32 add reduction (portable shuffle butterfly)
__device__ __forceinline__ float warp_sum(float x) {
#pragma unroll
    for (int off = 16; off; off >>= 1) x += __shfl_xor_sync(0xffffffffu, x, off);
    return x;
}

// ---- cp.async helpers ----
__device__ __forceinline__ void cp16(uint32_t dst_smem, const void* src) {
    asm volatile("cp.async.cg.shared.global [%0], [%1], 16;" :: "r"(dst_smem), "l"(src));
}
__device__ __forceinline__ void cp_commit() {
    asm volatile("cp.async.commit_group;");
}
template <int N>
__device__ __forceinline__ void cp_wait() {
    asm volatile("cp.async.wait_group %0;" :: "n"(N));
}

// ================= kernel 1: prologue =================
// blocks [0,NB): per-video b — P for all 12 frames (w1p register-resident) + Gram.
// blocks [NB,NB+NA): per-text a — Tpart packed + inverse norms.
__global__ __launch_bounds__(256, 2) void k_pre(const float* __restrict__ text,
                                                const float* __restrict__ video,
                                                const float* __restrict__ W1,
                                                const float* __restrict__ b1) {
    __shared__ __align__(16) float sm[NV * ND];  // 24 KB, aliased per role
    const int bid = blockIdx.x, t = threadIdx.x;

    if (bid < NB) {
        const int b = bid;
        // stage all 12 video rows once
        {
            const float4* vsrc = (const float4*)(video + b * NV * ND);
            float4* vdst = (float4*)sm;
            for (int i = t; i < NV * ND / 4; i += 256) vdst[i] = __ldg(vsrc + i);
        }
        __syncthreads();

        // W1 video column for hidden unit t, packed over w — loaded ONCE per block
        unsigned long long w1p[NW / 2];
#pragma unroll
        for (int w = 0; w < NW / 2; w++)
            w1p[w] = pk2(__ldg(&W1[(NW + 2 * w) * NH + t]),
                         __ldg(&W1[(NW + 2 * w + 1) * NH + t]));

        for (int v = 0; v < NV; v++) {
#pragma unroll
            for (int c = 0; c < NC; c++) {
                unsigned long long accA = 0ULL, accB = 0ULL;
                const ulonglong2* vr = (const ulonglong2*)(sm + v * ND + c * NW);
#pragma unroll
                for (int q = 0; q < NW / 4; q++) {
                    ulonglong2 x = vr[q];
                    accA = ffma2(x.x, w1p[2 * q], accA);
                    accB = ffma2(x.y, w1p[2 * q + 1], accB);
                }
                float a0, a1, b0, b1;
                upk2(accA, a0, a1); upk2(accB, b0, b1);
                g_P[((b * NV + v) * NC + c) * NH + t] = (a0 + b0) + (a1 + b1);
            }
        }

        // Gram from staged rows — lane-rotated w to avoid same-bank serialization
        const int lane = t & 31;
        for (int idx = t; idx < NC * NV * NV; idx += 256) {
            int c  = idx / (NV * NV);
            int r  = idx % (NV * NV);
            int v1 = r / NV, v2 = r % NV;
            const float* p1 = sm + v1 * ND + c * NW;
            const float* p2 = sm + v2 * ND + c * NW;
            float acc = 0.0f;
#pragma unroll
            for (int w0 = 0; w0 < NW; w0++) {
                int w = (w0 + lane * 2) & (NW - 1);
                acc = fmaf(p1[w], p2[w], acc);
            }
            g_G[b * NC * NV * NV + idx] = acc;
        }
    } else {
        // ---- text path: Tpart packed + inverse norms ----
        const int a = bid - NB;
        float* trow  = sm;        // 512 floats
        float* stage = sm + 512;  // 8*264 floats
        trow[t]       = text[a * ND + t];
        trow[t + 256] = text[a * ND + 256 + t];
        __syncthreads();

        float w1t[NW];
#pragma unroll
        for (int w = 0; w < NW; w++) w1t[w] = __ldg(&W1[w * NH + t]);
        const float bb = __ldg(&b1[t]);
        const int kk = t >> 5, lane = t & 31;

#pragma unroll
        for (int c = 0; c < NC; c++) {
            float acc = bb;
#pragma unroll
            for (int w = 0; w < NW; w++) acc = fmaf(trow[c * NW + w], w1t[w], acc);
            stage[c * 264 + kk * 33 + lane] = acc;
        }

        float x1 = trow[kk * NW + lane];
        float x2 = trow[kk * NW + 32 + lane];
        float s = warp_sum(x1 * x1 + x2 * x2);
        if (lane == 0) g_invn[a * NC + kk] = rsqrtf(s);
        __syncthreads();

        for (int i = t; i < NC * NH; i += 256) {
            int c = i >> 8, r = i & 255;
            g_T[a * (NC * NH) + i] = stage[c * 264 + (r & 7) * 33 + (r >> 3)];
        }
    }
}

// ================= kernel 2: scores + softmax + cosine (cp.async pipelined) =================
#define TROW 68
#define TBUF (64 * TROW)
#define SCORE_SMEM_BYTES (20224 * 4)

__global__ __launch_bounds__(256, 2) void k_score(const float* __restrict__ text,
                                                  const float* __restrict__ video) {
    extern __shared__ __align__(16) float dyn[];
    float* T_sh    = dyn;
    float* V_sh    = dyn + 8704;
    float* G_sh    = dyn + 14848;
    float* w_sh    = dyn + 16000;
    float* invn_sh = dyn + 16768;
    float* logit_sh= dyn + 17280;
    float* np_sh   = dyn + 18112;

    const int t = threadIdx.x;
    const int b = blockIdx.y;
    const int a0 = blockIdx.x * 64;
    const int al = t & 63, vg = t >> 6;

    const int lrow = t >> 2, lpart = t & 3;
    const float* tg = text + (a0 + lrow) * ND + lpart * 16;
    uint32_t ts_addr[2];
#pragma unroll
    for (int bu = 0; bu < 2; bu++)
        ts_addr[bu] = (uint32_t)__cvta_generic_to_shared(
            &T_sh[bu * TBUF + lrow * TROW + lpart * 16]);

#pragma unroll
    for (int k = 0; k < 4; k++) cp16(ts_addr[0] + k * 16, tg + k * 4);
    cp_commit();

    {
        const float4* vsrc = (const float4*)(video + b * NV * ND);
        float4* vdst = (float4*)V_sh;
        for (int i = t; i < NV * ND / 4; i += 256) vdst[i] = __ldg(vsrc + i);
    }
    for (int i = t; i < NC * NV * NV; i += 256) G_sh[i] = g_G[b * NC * NV * NV + i];
    for (int i = t; i < 64 * NC; i += 256) invn_sh[i] = g_invn[a0 * NC + i];

    float S[3][NC];
#pragma unroll
    for (int c = 0; c < NC; c++) {
        if (c < 7) {
#pragma unroll
            for (int k = 0; k < 4; k++)
                cp16(ts_addr[(c + 1) & 1] + k * 16, tg + (c + 1) * 64 + k * 4);
            cp_commit();
            cp_wait<1>();
        } else {
            cp_wait<0>();
        }
        __syncthreads();

        const float* Tb = T_sh + (c & 1) * TBUF;
        unsigned long long accA[3] = {0ULL, 0ULL, 0ULL};
        unsigned long long accB[3] = {0ULL, 0ULL, 0ULL};
#pragma unroll
        for (int q = 0; q < 16; q++) {
            ulonglong2 tr = *(const ulonglong2*)&Tb[al * TROW + q * 4];
#pragma unroll
            for (int j = 0; j < 3; j++) {
                ulonglong2 vd = *(const ulonglong2*)&V_sh[(vg * 3 + j) * ND + c * NW + q * 4];
                accA[j] = ffma2(tr.x, vd.x, accA[j]);
                accB[j] = ffma2(tr.y, vd.y, accB[j]);
            }
        }
#pragma unroll
        for (int j = 0; j < 3; j++) {
            float x0, x1, y0, y1;
            upk2(accA[j], x0, x1); upk2(accB[j], y0, y1);
            S[j][c] = (x0 + y0) + (x1 + y1);
        }
        __syncthreads();
    }

#pragma unroll
    for (int j = 0; j < 3; j++) {
        float l = 0.0f;
#pragma unroll
        for (int c = 0; c < NC; c++) l += S[j][c];
        logit_sh[al * 13 + vg * 3 + j] = l;
    }
    __syncthreads();

    if (t < 64) {
        float s[NV], m = -1e30f;
#pragma unroll
        for (int v = 0; v < NV; v++) {
            s[v] = logit_sh[t * 13 + v] * TEMP_INV;
            m = fmaxf(m, s[v]);
        }
        float tot = 0.0f;
#pragma unroll
        for (int v = 0; v < NV; v++) { s[v] = __expf(s[v] - m); tot += s[v]; }
        float inv = 1.0f / tot;
#pragma unroll
        for (int v = 0; v < NV; v++) w_sh[t * NV + v] = s[v] * inv;
    }
    __syncthreads();

    {
        float wj[3];
#pragma unroll
        for (int j = 0; j < 3; j++) wj[j] = w_sh[al * NV + vg * 3 + j];
#pragma unroll
        for (int c = 0; c < NC; c++) {
            float acc = wj[0] * S[0][c];
            acc = fmaf(wj[1], S[1][c], acc);
            acc = fmaf(wj[2], S[2][c], acc);
            np_sh[al * 33 + vg * 8 + c] = acc;
        }
    }
    __syncthreads();

    for (int idx = t; idx < 512; idx += 256) {
        int aa = idx >> 3, cc = idx & 7;
        float wv[NV];
#pragma unroll
        for (int v = 0; v < NV; v++) wv[v] = w_sh[aa * NV + v];
        float num = (np_sh[aa * 33 + cc] + np_sh[aa * 33 + 8 + cc]) +
                    (np_sh[aa * 33 + 16 + cc] + np_sh[aa * 33 + 24 + cc]);
        float den = 0.0f;
#pragma unroll
        for (int v1 = 0; v1 < NV; v1++) {
            float ds = 0.0f;
#pragma unroll
            for (int v2 = 0; v2 < NV; v2++)
                ds = fmaf(wv[v2], G_sh[cc * NV * NV + v1 * NV + v2], ds);
            den = fmaf(wv[v1], ds, den);
        }
        g_cos[(b * NA + a0 + aa) * NC + cc] = num * invn_sh[aa * NC + cc] * rsqrtf(den);
    }
    for (int i = t; i < 64 * NV; i += 256) g_w[(b * NA + a0) * NV + i] = w_sh[i];
}

// ================= kernel 3: MLP gating main loop (1024 threads, f32x2) =================
// grid (4, NB), 1024 threads. warp = (center c, quarter q); lane owns h pair
// k = {2q, 2q+1}, h = 32k + lane. One f32x2 accumulator per thread.
__global__ __launch_bounds__(1024, 1) void k_main(const float* __restrict__ W2,
                                                  const float* __restrict__ b2,
                                                  float* __restrict__ out) {
    __shared__ __align__(16) float2 wd_sh[64 * NV];  // duplicated packed weights, 6 KB
    __shared__ float cos_sh[64 * NC];
    __shared__ float part_sh[64][32];

    const int t = threadIdx.x;
    const int b = blockIdx.y;
    const int a0 = blockIdx.x * 64;
    const int lane = t & 31, wq = t >> 5;
    const int c = wq >> 2, qtr = wq & 3;

    for (int i = t; i < 64 * NV; i += 1024) {
        float wv = g_w[(b * NA + a0) * NV + i];
        wd_sh[i] = make_float2(wv, wv);
    }
    for (int i = t; i < 64 * NC; i += 1024) cos_sh[i] = g_cos[(b * NA + a0) * NC + i];

    unsigned long long pp[NV];
#pragma unroll
    for (int v = 0; v < NV; v++) {
        const float* base = &g_P[((b * NV + v) * NC + c) * NH + lane];
        pp[v] = pk2(base[32 * (2 * qtr)], base[32 * (2 * qtr + 1)]);
    }
    const float w2lo = __ldg(&W2[32 * (2 * qtr) + lane]);
    const float w2hi = __ldg(&W2[32 * (2 * qtr + 1) + lane]);
    const float b2v = __ldg(&b2[0]);
    __syncthreads();

    const float* tb = g_T + (a0 * NC + c) * NH + lane * 8 + qtr * 2;
    unsigned long long t0 = *(const unsigned long long*)tb;
    unsigned long long t1 = *(const unsigned long long*)(tb + NC * NH);

#pragma unroll 2
    for (int ia = 0; ia < 64; ia++) {
        unsigned long long acc = t0;
        t0 = t1;
        int nia = (ia < 62) ? ia + 2 : 63;
        t1 = *(const unsigned long long*)(tb + nia * (NC * NH));  // prefetch dist 2

        const ulonglong2* wrow = (const ulonglong2*)&wd_sh[ia * NV];
#pragma unroll
        for (int vq = 0; vq < 6; vq++) {
            ulonglong2 wp = wrow[vq];
            acc = ffma2(wp.x, pp[2 * vq], acc);
            acc = ffma2(wp.y, pp[2 * vq + 1], acc);
        }
        float f0, f1;
        upk2(acc, f0, f1);
        float g = fmaxf(f0, 0.0f) * w2lo;
        g = fmaf(fmaxf(f1, 0.0f), w2hi, g);
        g = warp_sum(g);
        if (lane == 0) part_sh[ia][c * 4 + qtr] = g;
    }
    __syncthreads();

    if (t < 64) {
        float sum = 0.0f;
#pragma unroll
        for (int c2 = 0; c2 < NC; c2++) {
            float gsum = (part_sh[t][4 * c2] + part_sh[t][4 * c2 + 1]) +
                         (part_sh[t][4 * c2 + 2] + part_sh[t][4 * c2 + 3]);
            sum += (gsum + b2v) * cos_sh[t * NC + c2];
        }
        out[(a0 + t) * NB + b] = sum;
    }
}

extern "C" void kernel_launch(void* const* d_in, const int* in_sizes, int n_in,
                              void* d_out, int out_size) {
    const float* text  = (const float*)d_in[0];
    const float* video = (const float*)d_in[1];
    const float* W1    = (const float*)d_in[2];
    const float* b1    = (const float*)d_in[3];
    const float* W2    = (const float*)d_in[4];
    const float* b2    = (const float*)d_in[5];
    float* out = (float*)d_out;

    cudaFuncSetAttribute(k_score, cudaFuncAttributeMaxDynamicSharedMemorySize,
                         SCORE_SMEM_BYTES);

    k_pre<<<NB + NA, 256>>>(text, video, W1, b1);
    k_score<<<dim3(4, NB), 256, SCORE_SMEM_BYTES>>>(text, video);
    k_main<<<dim3(4, NB), 1024>>>(W2, b2, out);
}

// round 9
// speedup vs baseline: 1.3064x; 1.3064x over previous
#include <cuda_runtime.h>
#include <cstdint>

#define NA 256
#define NB 256
#define NV 12
#define ND 512
#define NC 8
#define NW 64
#define NH 256
#define TEMP_INV 0.2f

// ---- scratch (device globals; no allocation allowed) ----
__device__ __align__(16) float g_P[NB * NV * NC * NH];   // 25 MB [b][v][c][h]
__device__ __align__(16) float g_T[NA * NC * NH];        // 2 MB  [a][c][lane*8+k] packed
__device__ float g_invn[NA * NC];                        // 1/||t_chunk||
__device__ float g_G[NB * NC * NV * NV];                 // 1.2 MB chunk Gram
__device__ __align__(16) float g_w[NB * NA * NV];        // 3 MB softmax weights
__device__ __align__(16) float g_cos[NB * NA * NC];      // 2 MB cosine logits

// ---- packed f32x2 helpers ----
__device__ __forceinline__ unsigned long long pk2(float lo, float hi) {
    unsigned long long r;
    asm("mov.b64 %0, {%1, %2};" : "=l"(r) : "f"(lo), "f"(hi));
    return r;
}
__device__ __forceinline__ void upk2(unsigned long long p, float& lo, float& hi) {
    asm("mov.b64 {%0, %1}, %2;" : "=f"(lo), "=f"(hi) : "l"(p));
}
__device__ __forceinline__ unsigned long long ffma2(unsigned long long a, unsigned long long b,
                                                    unsigned long long c) {
    unsigned long long d;
    asm("fma.rn.f32x2 %0, %1, %2, %3;" : "=l"(d) : "l"(a), "l"(b), "l"(c));
    return d;
}
__device__ __forceinline__ float warp_sum(float x) {
#pragma unroll
    for (int off = 16; off; off >>= 1) x += __shfl_xor_sync(0xffffffffu, x, off);
    return x;
}

// ---- cp.async helpers ----
__device__ __forceinline__ void cp16(uint32_t dst_smem, const void* src) {
    asm volatile("cp.async.cg.shared.global [%0], [%1], 16;" :: "r"(dst_smem), "l"(src));
}
__device__ __forceinline__ void cp_commit() {
    asm volatile("cp.async.commit_group;");
}
template <int N>
__device__ __forceinline__ void cp_wait() {
    asm volatile("cp.async.wait_group %0;" :: "n"(N));
}

// ================= kernel 1: prologue =================
__global__ __launch_bounds__(256, 2) void k_pre(const float* __restrict__ text,
                                                const float* __restrict__ video,
                                                const float* __restrict__ W1,
                                                const float* __restrict__ b1) {
    __shared__ __align__(16) float sm[NV * ND];  // 24 KB, aliased per role
    const int bid = blockIdx.x, t = threadIdx.x;

    if (bid < NB) {
        const int b = bid;
        {
            const float4* vsrc = (const float4*)(video + b * NV * ND);
            float4* vdst = (float4*)sm;
            for (int i = t; i < NV * ND / 4; i += 256) vdst[i] = __ldg(vsrc + i);
        }
        __syncthreads();

        unsigned long long w1p[NW / 2];
#pragma unroll
        for (int w = 0; w < NW / 2; w++)
            w1p[w] = pk2(__ldg(&W1[(NW + 2 * w) * NH + t]),
                         __ldg(&W1[(NW + 2 * w + 1) * NH + t]));

        for (int v = 0; v < NV; v++) {
#pragma unroll
            for (int c = 0; c < NC; c++) {
                unsigned long long accA = 0ULL, accB = 0ULL;
                const ulonglong2* vr = (const ulonglong2*)(sm + v * ND + c * NW);
#pragma unroll
                for (int q = 0; q < NW / 4; q++) {
                    ulonglong2 x = vr[q];
                    accA = ffma2(x.x, w1p[2 * q], accA);
                    accB = ffma2(x.y, w1p[2 * q + 1], accB);
                }
                float a0, a1, b0, b1;
                upk2(accA, a0, a1); upk2(accB, b0, b1);
                g_P[((b * NV + v) * NC + c) * NH + t] = (a0 + b0) + (a1 + b1);
            }
        }

        // Gram — lane-rotated w to avoid same-bank serialization
        const int lane = t & 31;
        for (int idx = t; idx < NC * NV * NV; idx += 256) {
            int c  = idx / (NV * NV);
            int r  = idx % (NV * NV);
            int v1 = r / NV, v2 = r % NV;
            const float* p1 = sm + v1 * ND + c * NW;
            const float* p2 = sm + v2 * ND + c * NW;
            float acc = 0.0f;
#pragma unroll
            for (int w0 = 0; w0 < NW; w0++) {
                int w = (w0 + lane * 2) & (NW - 1);
                acc = fmaf(p1[w], p2[w], acc);
            }
            g_G[b * NC * NV * NV + idx] = acc;
        }
    } else {
        const int a = bid - NB;
        float* trow  = sm;
        float* stage = sm + 512;
        trow[t]       = text[a * ND + t];
        trow[t + 256] = text[a * ND + 256 + t];
        __syncthreads();

        float w1t[NW];
#pragma unroll
        for (int w = 0; w < NW; w++) w1t[w] = __ldg(&W1[w * NH + t]);
        const float bb = __ldg(&b1[t]);
        const int kk = t >> 5, lane = t & 31;

#pragma unroll
        for (int c = 0; c < NC; c++) {
            float acc = bb;
#pragma unroll
            for (int w = 0; w < NW; w++) acc = fmaf(trow[c * NW + w], w1t[w], acc);
            stage[c * 264 + kk * 33 + lane] = acc;
        }

        float x1 = trow[kk * NW + lane];
        float x2 = trow[kk * NW + 32 + lane];
        float s = warp_sum(x1 * x1 + x2 * x2);
        if (lane == 0) g_invn[a * NC + kk] = rsqrtf(s);
        __syncthreads();

        for (int i = t; i < NC * NH; i += 256) {
            int c = i >> 8, r = i & 255;
            g_T[a * (NC * NH) + i] = stage[c * 264 + (r & 7) * 33 + (r >> 3)];
        }
    }
}

// ================= kernel 2: scores + softmax + cosine (3-stage cp.async) =================
#define TROW 68
#define TBUF (64 * TROW)  // 4352 floats / buffer, 3 buffers
// float offsets: T 0..13056, V 13056, G 19200, w 20352, invn 21120, logit 21632, np 22464
#define SCORE_SMEM_BYTES (24576 * 4)

__global__ __launch_bounds__(256, 2) void k_score(const float* __restrict__ text,
                                                  const float* __restrict__ video) {
    extern __shared__ __align__(16) float dyn[];
    float* T_sh    = dyn;
    float* V_sh    = dyn + 13056;
    float* G_sh    = dyn + 19200;
    float* w_sh    = dyn + 20352;
    float* invn_sh = dyn + 21120;
    float* logit_sh= dyn + 21632;
    float* np_sh   = dyn + 22464;

    const int t = threadIdx.x;
    const int b = blockIdx.y;
    const int a0 = blockIdx.x * 64;
    const int al = t & 63, vg = t >> 6;

    const int lrow = t >> 2, lpart = t & 3;
    const float* tg = text + (a0 + lrow) * ND + lpart * 16;
    uint32_t ts_addr[3];
#pragma unroll
    for (int bu = 0; bu < 3; bu++)
        ts_addr[bu] = (uint32_t)__cvta_generic_to_shared(
            &T_sh[bu * TBUF + lrow * TROW + lpart * 16]);

    // prologue: prefetch chunks 0 and 1 (one commit-group each)
#pragma unroll
    for (int k = 0; k < 4; k++) cp16(ts_addr[0] + k * 16, tg + k * 4);
    cp_commit();
#pragma unroll
    for (int k = 0; k < 4; k++) cp16(ts_addr[1] + k * 16, tg + NW + k * 4);
    cp_commit();

    {
        const float4* vsrc = (const float4*)(video + b * NV * ND);
        float4* vdst = (float4*)V_sh;
        for (int i = t; i < NV * ND / 4; i += 256) vdst[i] = __ldg(vsrc + i);
    }
    for (int i = t; i < NC * NV * NV; i += 256) G_sh[i] = g_G[b * NC * NV * NV + i];
    for (int i = t; i < 64 * NC; i += 256) invn_sh[i] = g_invn[a0 * NC + i];

    float S[3][NC];
#pragma unroll
    for (int c = 0; c < NC; c++) {
        if (c < 7) cp_wait<1>(); else cp_wait<0>();
        __syncthreads();  // single barrier per chunk: data ready + prior buffer freed
        if (c < 6) {      // prefetch c+2 into buffer (c+2)%3
            int nb = (c + 2) % 3;
#pragma unroll
            for (int k = 0; k < 4; k++) cp16(ts_addr[nb] + k * 16, tg + (c + 2) * NW + k * 4);
            cp_commit();
        }

        const float* Tb = T_sh + (c % 3) * TBUF;
        unsigned long long accA[3] = {0ULL, 0ULL, 0ULL};
        unsigned long long accB[3] = {0ULL, 0ULL, 0ULL};
#pragma unroll
        for (int q = 0; q < 16; q++) {
            ulonglong2 tr = *(const ulonglong2*)&Tb[al * TROW + q * 4];
#pragma unroll
            for (int j = 0; j < 3; j++) {
                ulonglong2 vd = *(const ulonglong2*)&V_sh[(vg * 3 + j) * ND + c * NW + q * 4];
                accA[j] = ffma2(tr.x, vd.x, accA[j]);
                accB[j] = ffma2(tr.y, vd.y, accB[j]);
            }
        }
#pragma unroll
        for (int j = 0; j < 3; j++) {
            float x0, x1, y0, y1;
            upk2(accA[j], x0, x1); upk2(accB[j], y0, y1);
            S[j][c] = (x0 + y0) + (x1 + y1);
        }
    }

#pragma unroll
    for (int j = 0; j < 3; j++) {
        float l = 0.0f;
#pragma unroll
        for (int c = 0; c < NC; c++) l += S[j][c];
        logit_sh[al * 13 + vg * 3 + j] = l;
    }
    __syncthreads();

    if (t < 64) {
        float s[NV], m = -1e30f;
#pragma unroll
        for (int v = 0; v < NV; v++) {
            s[v] = logit_sh[t * 13 + v] * TEMP_INV;
            m = fmaxf(m, s[v]);
        }
        float tot = 0.0f;
#pragma unroll
        for (int v = 0; v < NV; v++) { s[v] = __expf(s[v] - m); tot += s[v]; }
        float inv = 1.0f / tot;
#pragma unroll
        for (int v = 0; v < NV; v++) w_sh[t * NV + v] = s[v] * inv;
    }
    __syncthreads();

    {
        float wj[3];
#pragma unroll
        for (int j = 0; j < 3; j++) wj[j] = w_sh[al * NV + vg * 3 + j];
#pragma unroll
        for (int c = 0; c < NC; c++) {
            float acc = wj[0] * S[0][c];
            acc = fmaf(wj[1], S[1][c], acc);
            acc = fmaf(wj[2], S[2][c], acc);
            np_sh[al * 33 + vg * 8 + c] = acc;
        }
    }
    __syncthreads();

    for (int idx = t; idx < 512; idx += 256) {
        int aa = idx >> 3, cc = idx & 7;
        float wv[NV];
#pragma unroll
        for (int v = 0; v < NV; v++) wv[v] = w_sh[aa * NV + v];
        float num = (np_sh[aa * 33 + cc] + np_sh[aa * 33 + 8 + cc]) +
                    (np_sh[aa * 33 + 16 + cc] + np_sh[aa * 33 + 24 + cc]);
        float den = 0.0f;
#pragma unroll
        for (int v1 = 0; v1 < NV; v1++) {
            float ds = 0.0f;
#pragma unroll
            for (int v2 = 0; v2 < NV; v2++)
                ds = fmaf(wv[v2], G_sh[cc * NV * NV + v1 * NV + v2], ds);
            den = fmaf(wv[v1], ds, den);
        }
        g_cos[(b * NA + a0 + aa) * NC + cc] = num * invn_sh[aa * NC + cc] * rsqrtf(den);
    }
    for (int i = t; i < 64 * NV; i += 256) g_w[(b * NA + a0) * NV + i] = w_sh[i];
}

// ================= kernel 3: MLP gating (512 thr, f32x2, 3-step reduce) =================
__global__ __launch_bounds__(512, 1) void k_main(const float* __restrict__ W2,
                                                 const float* __restrict__ b2,
                                                 float* __restrict__ out) {
    __shared__ __align__(16) float2 wd_sh[64 * NV];
    __shared__ float cos_sh[64 * NC];
    __shared__ float part_sh[64][64];  // [ia][(c*2+half)*4 + lane<4]

    const int t = threadIdx.x;
    const int b = blockIdx.y;
    const int a0 = blockIdx.x * 64;
    const int lane = t & 31, w16 = t >> 5;
    const int c = w16 >> 1, half = w16 & 1;

    for (int i = t; i < 64 * NV; i += 512) {
        float wv = g_w[(b * NA + a0) * NV + i];
        wd_sh[i] = make_float2(wv, wv);
    }
    for (int i = t; i < 64 * NC; i += 512) cos_sh[i] = g_cos[(b * NA + a0) * NC + i];

    unsigned long long pp[NV][2];
#pragma unroll
    for (int v = 0; v < NV; v++)
#pragma unroll
        for (int jp = 0; jp < 2; jp++) {
            const float* base = &g_P[((b * NV + v) * NC + c) * NH + lane];
            pp[v][jp] = pk2(base[32 * (half * 4 + 2 * jp)], base[32 * (half * 4 + 2 * jp + 1)]);
        }
    float w2r[4];
#pragma unroll
    for (int j = 0; j < 4; j++) w2r[j] = __ldg(&W2[32 * (half * 4 + j) + lane]);
    const float b2v = __ldg(&b2[0]);
    __syncthreads();

    const float* tb = g_T + (a0 * NC + c) * NH + lane * 8 + half * 4;
    ulonglong2 t0 = *(const ulonglong2*)tb;
    ulonglong2 t1 = *(const ulonglong2*)(tb + NC * NH);

#pragma unroll 2
    for (int ia = 0; ia < 64; ia++) {
        unsigned long long a01 = t0.x, a23 = t0.y;
        t0 = t1;
        int nia = (ia < 62) ? ia + 2 : 63;
        t1 = *(const ulonglong2*)(tb + nia * (NC * NH));

        const ulonglong2* wrow = (const ulonglong2*)&wd_sh[ia * NV];
#pragma unroll
        for (int vq = 0; vq < 6; vq++) {
            ulonglong2 wp = wrow[vq];
            a01 = ffma2(wp.x, pp[2 * vq][0], a01);
            a23 = ffma2(wp.x, pp[2 * vq][1], a23);
            a01 = ffma2(wp.y, pp[2 * vq + 1][0], a01);
            a23 = ffma2(wp.y, pp[2 * vq + 1][1], a23);
        }
        float f0, f1, f2, f3;
        upk2(a01, f0, f1); upk2(a23, f2, f3);
        float g = fmaxf(f0, 0.0f) * w2r[0];
        g = fmaf(fmaxf(f1, 0.0f), w2r[1], g);
        g = fmaf(fmaxf(f2, 0.0f), w2r[2], g);
        g = fmaf(fmaxf(f3, 0.0f), w2r[3], g);
        // 3-step butterfly: lanes 0-3 hold disjoint partials covering all 32 lanes
        g += __shfl_xor_sync(0xffffffffu, g, 16);
        g += __shfl_xor_sync(0xffffffffu, g, 8);
        g += __shfl_xor_sync(0xffffffffu, g, 4);
        if (lane < 4) part_sh[ia][w16 * 4 + lane] = g;
    }
    __syncthreads();

    if (t < 64) {
        float sum = 0.0f;
#pragma unroll
        for (int c2 = 0; c2 < NC; c2++) {
            const float* pr = &part_sh[t][c2 * 8];
            float gsum = ((pr[0] + pr[1]) + (pr[2] + pr[3])) +
                         ((pr[4] + pr[5]) + (pr[6] + pr[7]));
            sum += (gsum + b2v) * cos_sh[t * NC + c2];
        }
        out[(a0 + t) * NB + b] = sum;
    }
}

extern "C" void kernel_launch(void* const* d_in, const int* in_sizes, int n_in,
                              void* d_out, int out_size) {
    const float* text  = (const float*)d_in[0];
    const float* video = (const float*)d_in[1];
    const float* W1    = (const float*)d_in[2];
    const float* b1    = (const float*)d_in[3];
    const float* W2    = (const float*)d_in[4];
    const float* b2    = (const float*)d_in[5];
    float* out = (float*)d_out;

    cudaFuncSetAttribute(k_score, cudaFuncAttributeMaxDynamicSharedMemorySize,
                         SCORE_SMEM_BYTES);

    k_pre<<<NB + NA, 256>>>(text, video, W1, b1);
    k_score<<<dim3(4, NB), 256, SCORE_SMEM_BYTES>>>(text, video);
    k_main<<<dim3(4, NB), 512>>>(W2, b2, out);
}